// round 2
// baseline (speedup 1.0000x reference)
#include <cuda_runtime.h>
#include <math.h>

// Problem constants
#define S_LEN   4096
#define DMODEL  1024
#define NHEAD   16
#define HDIM    64
#define N3      3072   // 3 * DMODEL

// Scratch buffers (allocation-free rule: __device__ globals)
__device__ float g_qkv[S_LEN * N3];      // [4096, 3072]  q|k|v
__device__ float g_attn[S_LEN * DMODEL]; // [4096, 1024]  attention output (s, h*64+d)

// ---------------------------------------------------------------------------
// Classic register-blocked SGEMM: C[M,N] = A[M,K] @ B[K,N] + bias[N]
// BM=BN=128, BK=8, 256 threads, 8x8 micro-tile per thread, float4 loads.
// M,N multiples of 128; K multiple of 8. No bounds checks needed here.
// ---------------------------------------------------------------------------
template<int BM, int BN, int BK, int TM, int TN>
__global__ void __launch_bounds__(256)
sgemm_bias_kernel(const float* __restrict__ A,
                  const float* __restrict__ B,
                  const float* __restrict__ bias,
                  float* __restrict__ C,
                  int M, int N, int K) {
    __shared__ float As[BK][BM];   // transposed A tile
    __shared__ float Bs[BK][BN];

    const int tid  = threadIdx.x;
    const int cRow = blockIdx.y;
    const int cCol = blockIdx.x;

    const int threadRow = tid / (BN / TN);   // 0..15
    const int threadCol = tid % (BN / TN);   // 0..15

    // A tile loads: BM x BK = 1024 floats, 256 threads -> 1 float4 each
    const int aRow = tid / (BK / 4);         // 0..127
    const int aCol = (tid % (BK / 4)) * 4;   // 0 or 4
    // B tile loads: BK x BN = 1024 floats
    const int bRow = tid / (BN / 4);         // 0..7
    const int bCol = (tid % (BN / 4)) * 4;   // 0..124

    const float* Ab = A + (size_t)cRow * BM * K;
    const float* Bb = B + (size_t)cCol * BN;

    float acc[TM][TN];
    #pragma unroll
    for (int i = 0; i < TM; i++)
        #pragma unroll
        for (int j = 0; j < TN; j++) acc[i][j] = 0.0f;

    float regM[TM], regN[TN];

    for (int kb = 0; kb < K; kb += BK) {
        float4 a4 = *reinterpret_cast<const float4*>(Ab + (size_t)aRow * K + kb + aCol);
        As[aCol + 0][aRow] = a4.x;
        As[aCol + 1][aRow] = a4.y;
        As[aCol + 2][aRow] = a4.z;
        As[aCol + 3][aRow] = a4.w;
        float4 b4 = *reinterpret_cast<const float4*>(Bb + (size_t)(kb + bRow) * N + bCol);
        *reinterpret_cast<float4*>(&Bs[bRow][bCol]) = b4;
        __syncthreads();

        #pragma unroll
        for (int k = 0; k < BK; k++) {
            #pragma unroll
            for (int i = 0; i < TM; i++) regM[i] = As[k][threadRow * TM + i];
            #pragma unroll
            for (int j = 0; j < TN; j++) regN[j] = Bs[k][threadCol * TN + j];
            #pragma unroll
            for (int i = 0; i < TM; i++)
                #pragma unroll
                for (int j = 0; j < TN; j++)
                    acc[i][j] += regM[i] * regN[j];
        }
        __syncthreads();
    }

    #pragma unroll
    for (int i = 0; i < TM; i++) {
        int row = cRow * BM + threadRow * TM + i;
        #pragma unroll
        for (int j = 0; j < TN; j += 4) {
            int col = cCol * BN + threadCol * TN + j;
            float4 o;
            o.x = acc[i][j + 0] + bias[col + 0];
            o.y = acc[i][j + 1] + bias[col + 1];
            o.z = acc[i][j + 2] + bias[col + 2];
            o.w = acc[i][j + 3] + bias[col + 3];
            *reinterpret_cast<float4*>(C + (size_t)row * N + col) = o;
        }
    }
}

// ---------------------------------------------------------------------------
// Flash attention, fp32, causal. One CTA per (q-tile of 64 rows, head).
// Br=Bc=64. 256 threads as 16x16; each thread owns a 4x4 micro-tile of the
// 64x64 score/output blocks. Online softmax with shfl-xor row reductions
// across the 16 threads sharing a row group.
// Q/K/V are strided views into g_qkv: q cols [0,1024), k [1024,2048), v [2048,3072).
// ---------------------------------------------------------------------------
#define QS_LD 65
#define VS_LD 68
#define FLASH_SMEM_BYTES ((2 * 64 * QS_LD + 2 * 64 * VS_LD) * 4)  // 68096

__global__ void __launch_bounds__(256)
flash_attn_kernel(const float* __restrict__ qkv,
                  float* __restrict__ outp) {
    extern __shared__ float smem[];
    float* Qs = smem;                    // 64 x 65
    float* Ks = Qs + 64 * QS_LD;         // 64 x 65
    float* Ps = Ks + 64 * QS_LD;         // 64 x 68
    float* Vs = Ps + 64 * VS_LD;         // 64 x 68

    const int qb = blockIdx.x;           // 0..63
    const int h  = blockIdx.y;           // 0..15
    const int tid = threadIdx.x;
    const int tr = tid >> 4;             // 0..15 (row group)
    const int tc = tid & 15;             // 0..15 (col group)

    const float scale = 0.125f;          // 1/sqrt(64)
    const int qcol = h * HDIM;           // q column base
    const int kcol = DMODEL + h * HDIM;
    const int vcol = 2 * DMODEL + h * HDIM;

    // Load Q tile (scaled). 64 rows x 16 float4.
    for (int i = tid; i < 64 * 16; i += 256) {
        int r  = i >> 4;
        int c4 = (i & 15) * 4;
        float4 q4 = *reinterpret_cast<const float4*>(
            qkv + (size_t)(qb * 64 + r) * N3 + qcol + c4);
        Qs[r * QS_LD + c4 + 0] = q4.x * scale;
        Qs[r * QS_LD + c4 + 1] = q4.y * scale;
        Qs[r * QS_LD + c4 + 2] = q4.z * scale;
        Qs[r * QS_LD + c4 + 3] = q4.w * scale;
    }

    float m_i[4], l_i[4], O[4][4];
    #pragma unroll
    for (int i = 0; i < 4; i++) {
        m_i[i] = -1e30f;
        l_i[i] = 0.0f;
        #pragma unroll
        for (int j = 0; j < 4; j++) O[i][j] = 0.0f;
    }

    // Per-thread smem row base pointers (hoisted out of the k-loops)
    const float* Qrow0 = Qs + (tr * 4 + 0) * QS_LD;
    const float* Qrow1 = Qs + (tr * 4 + 1) * QS_LD;
    const float* Qrow2 = Qs + (tr * 4 + 2) * QS_LD;
    const float* Qrow3 = Qs + (tr * 4 + 3) * QS_LD;

    for (int kb = 0; kb <= qb; kb++) {
        __syncthreads();  // previous iter done reading Ks/Vs/Ps
        // Load K, V tiles
        for (int i = tid; i < 64 * 16; i += 256) {
            int r  = i >> 4;
            int c4 = (i & 15) * 4;
            const float* krow = qkv + (size_t)(kb * 64 + r) * N3;
            float4 k4 = *reinterpret_cast<const float4*>(krow + kcol + c4);
            Ks[r * QS_LD + c4 + 0] = k4.x;
            Ks[r * QS_LD + c4 + 1] = k4.y;
            Ks[r * QS_LD + c4 + 2] = k4.z;
            Ks[r * QS_LD + c4 + 3] = k4.w;
            float4 v4 = *reinterpret_cast<const float4*>(krow + vcol + c4);
            *reinterpret_cast<float4*>(&Vs[r * VS_LD + c4]) = v4;
        }
        __syncthreads();

        // S = Q K^T  (4x4 per thread)
        float s[4][4];
        #pragma unroll
        for (int i = 0; i < 4; i++)
            #pragma unroll
            for (int j = 0; j < 4; j++) s[i][j] = 0.0f;

        const float* Krow0 = Ks + (tc * 4 + 0) * QS_LD;
        const float* Krow1 = Ks + (tc * 4 + 1) * QS_LD;
        const float* Krow2 = Ks + (tc * 4 + 2) * QS_LD;
        const float* Krow3 = Ks + (tc * 4 + 3) * QS_LD;

        #pragma unroll 8
        for (int d = 0; d < HDIM; d++) {
            float qreg[4], kreg[4];
            qreg[0] = Qrow0[d]; qreg[1] = Qrow1[d];
            qreg[2] = Qrow2[d]; qreg[3] = Qrow3[d];
            kreg[0] = Krow0[d]; kreg[1] = Krow1[d];
            kreg[2] = Krow2[d]; kreg[3] = Krow3[d];
            #pragma unroll
            for (int i = 0; i < 4; i++)
                #pragma unroll
                for (int j = 0; j < 4; j++)
                    s[i][j] += qreg[i] * kreg[j];
        }

        // Causal mask (diagonal tile only)
        if (kb == qb) {
            #pragma unroll
            for (int i = 0; i < 4; i++) {
                int qrow = tr * 4 + i;
                #pragma unroll
                for (int j = 0; j < 4; j++) {
                    int kcol_l = tc * 4 + j;
                    if (kcol_l > qrow) s[i][j] = -1e30f;
                }
            }
        }

        // Online softmax update
        float alpha[4], m_new[4];
        #pragma unroll
        for (int i = 0; i < 4; i++) {
            float v = fmaxf(fmaxf(s[i][0], s[i][1]), fmaxf(s[i][2], s[i][3]));
            #pragma unroll
            for (int off = 8; off >= 1; off >>= 1)
                v = fmaxf(v, __shfl_xor_sync(0xffffffffu, v, off));
            m_new[i] = fmaxf(m_i[i], v);
            alpha[i] = __expf(m_i[i] - m_new[i]);
        }

        float p[4][4];
        #pragma unroll
        for (int i = 0; i < 4; i++) {
            float rs = 0.0f;
            #pragma unroll
            for (int j = 0; j < 4; j++) {
                p[i][j] = __expf(s[i][j] - m_new[i]);
                rs += p[i][j];
            }
            #pragma unroll
            for (int off = 8; off >= 1; off >>= 1)
                rs += __shfl_xor_sync(0xffffffffu, rs, off);
            l_i[i] = l_i[i] * alpha[i] + rs;
            m_i[i] = m_new[i];
            #pragma unroll
            for (int j = 0; j < 4; j++) O[i][j] *= alpha[i];
        }

        // Stage P for the PV product
        #pragma unroll
        for (int i = 0; i < 4; i++)
            #pragma unroll
            for (int j = 0; j < 4; j++)
                Ps[(tr * 4 + i) * VS_LD + tc * 4 + j] = p[i][j];
        __syncthreads();

        // O += P @ V
        #pragma unroll 4
        for (int k = 0; k < 64; k++) {
            float preg[4];
            #pragma unroll
            for (int i = 0; i < 4; i++) preg[i] = Ps[(tr * 4 + i) * VS_LD + k];
            float4 v4 = *reinterpret_cast<const float4*>(&Vs[k * VS_LD + tc * 4]);
            float vreg[4] = {v4.x, v4.y, v4.z, v4.w};
            #pragma unroll
            for (int i = 0; i < 4; i++)
                #pragma unroll
                for (int j = 0; j < 4; j++)
                    O[i][j] += preg[i] * vreg[j];
        }
    }

    // Epilogue: normalize and write [s, h*64+d]
    #pragma unroll
    for (int i = 0; i < 4; i++) {
        float inv_l = 1.0f / l_i[i];
        int row = qb * 64 + tr * 4 + i;
        float4 o;
        o.x = O[i][0] * inv_l;
        o.y = O[i][1] * inv_l;
        o.z = O[i][2] * inv_l;
        o.w = O[i][3] * inv_l;
        *reinterpret_cast<float4*>(outp + (size_t)row * DMODEL + h * HDIM + tc * 4) = o;
    }
}

// ---------------------------------------------------------------------------
// Launch
// ---------------------------------------------------------------------------
extern "C" void kernel_launch(void* const* d_in, const int* in_sizes, int n_in,
                              void* d_out, int out_size) {
    const float* x      = (const float*)d_in[0];
    const float* w_qkv  = (const float*)d_in[1];
    const float* b_qkv  = (const float*)d_in[2];
    const float* w_proj = (const float*)d_in[3];
    const float* b_proj = (const float*)d_in[4];
    float* out = (float*)d_out;

    float *qkv, *attn;
    cudaGetSymbolAddress((void**)&qkv, g_qkv);
    cudaGetSymbolAddress((void**)&attn, g_attn);

    // 1) QKV projection: [4096,1024] @ [1024,3072] + bias
    sgemm_bias_kernel<128, 128, 8, 8, 8>
        <<<dim3(N3 / 128, S_LEN / 128), 256>>>(x, w_qkv, b_qkv, qkv,
                                               S_LEN, N3, DMODEL);

    // 2) Causal flash attention
    cudaFuncSetAttribute(flash_attn_kernel,
                         cudaFuncAttributeMaxDynamicSharedMemorySize,
                         FLASH_SMEM_BYTES);
    flash_attn_kernel<<<dim3(S_LEN / 64, NHEAD), 256, FLASH_SMEM_BYTES>>>(qkv, attn);

    // 3) Output projection: [4096,1024] @ [1024,1024] + bias
    sgemm_bias_kernel<128, 128, 8, 8, 8>
        <<<dim3(DMODEL / 128, S_LEN / 128), 256>>>(attn, w_proj, b_proj, out,
                                                   S_LEN, DMODEL, DMODEL);
}

// round 5
// speedup vs baseline: 2.4494x; 2.4494x over previous
#include <cuda_runtime.h>
#include <cuda_bf16.h>
#include <cstdint>

// Problem constants
#define S_LEN   4096
#define DMODEL  1024
#define NHEAD   16
#define HDIM    64
#define N3      3072

// Scratch (__device__ globals per allocation-free rule)
__device__ float g_qkv[S_LEN * N3];
__device__ float g_attn[S_LEN * DMODEL];
__device__ __nv_bfloat16 g_xhi[S_LEN * DMODEL], g_xlo[S_LEN * DMODEL];
__device__ __nv_bfloat16 g_ahi[S_LEN * DMODEL], g_alo[S_LEN * DMODEL];
__device__ __nv_bfloat16 g_wqh[N3 * DMODEL],   g_wql[N3 * DMODEL];
__device__ __nv_bfloat16 g_wph[DMODEL * DMODEL], g_wpl[DMODEL * DMODEL];

// ---------------------------------------------------------------------------
// MMA wrappers (sm_80 baseline PTX -> HMMA; compiles for family target sm_103)
// ---------------------------------------------------------------------------
__device__ __forceinline__ void mma_bf16(float* c, const uint32_t* a, const uint32_t* b) {
    asm volatile(
        "mma.sync.aligned.m16n8k16.row.col.f32.bf16.bf16.f32 "
        "{%0,%1,%2,%3}, {%4,%5,%6,%7}, {%8,%9}, {%0,%1,%2,%3};"
        : "+f"(c[0]), "+f"(c[1]), "+f"(c[2]), "+f"(c[3])
        : "r"(a[0]), "r"(a[1]), "r"(a[2]), "r"(a[3]), "r"(b[0]), "r"(b[1]));
}

__device__ __forceinline__ void mma_tf32(float* c, const uint32_t* a, const uint32_t* b) {
    asm volatile(
        "mma.sync.aligned.m16n8k8.row.col.f32.tf32.tf32.f32 "
        "{%0,%1,%2,%3}, {%4,%5,%6,%7}, {%8,%9}, {%0,%1,%2,%3};"
        : "+f"(c[0]), "+f"(c[1]), "+f"(c[2]), "+f"(c[3])
        : "r"(a[0]), "r"(a[1]), "r"(a[2]), "r"(a[3]), "r"(b[0]), "r"(b[1]));
}

__device__ __forceinline__ uint32_t f2tf32(float x) {
    uint32_t r;
    asm("cvt.rna.tf32.f32 %0, %1;" : "=r"(r) : "f"(x));
    return r;
}

// ---------------------------------------------------------------------------
// Prep: fp32 -> bf16 hi/lo split (same layout).
// ---------------------------------------------------------------------------
__global__ void __launch_bounds__(256)
split_kernel(const float* __restrict__ in,
             __nv_bfloat16* __restrict__ hi, __nv_bfloat16* __restrict__ lo) {
    int i = (blockIdx.x * 256 + threadIdx.x) * 4;
    float4 v = *reinterpret_cast<const float4*>(in + i);
    __nv_bfloat16 h0 = __float2bfloat16(v.x), h1 = __float2bfloat16(v.y);
    __nv_bfloat16 h2 = __float2bfloat16(v.z), h3 = __float2bfloat16(v.w);
    __nv_bfloat162 ha; ha.x = h0; ha.y = h1;
    __nv_bfloat162 hb; hb.x = h2; hb.y = h3;
    __nv_bfloat162 la;
    la.x = __float2bfloat16(v.x - __bfloat162float(h0));
    la.y = __float2bfloat16(v.y - __bfloat162float(h1));
    __nv_bfloat162 lb;
    lb.x = __float2bfloat16(v.z - __bfloat162float(h2));
    lb.y = __float2bfloat16(v.w - __bfloat162float(h3));
    *reinterpret_cast<__nv_bfloat162*>(hi + i)     = ha;
    *reinterpret_cast<__nv_bfloat162*>(hi + i + 2) = hb;
    *reinterpret_cast<__nv_bfloat162*>(lo + i)     = la;
    *reinterpret_cast<__nv_bfloat162*>(lo + i + 2) = lb;
}

// ---------------------------------------------------------------------------
// Prep: W [Kd][Nd] fp32 -> hi/lo bf16 transposed [Nd][Kd]. Block (32,8).
// ---------------------------------------------------------------------------
__global__ void __launch_bounds__(256)
splitT_kernel(const float* __restrict__ W,
              __nv_bfloat16* __restrict__ hiT, __nv_bfloat16* __restrict__ loT,
              int Kd, int Nd) {
    __shared__ __nv_bfloat16 th[32][33];
    __shared__ __nv_bfloat16 tl[32][33];
    int n0 = blockIdx.x * 32, k0 = blockIdx.y * 32;
    int tx = threadIdx.x, ty = threadIdx.y;
    #pragma unroll
    for (int j = 0; j < 4; j++) {
        float v = W[(size_t)(k0 + ty + 8 * j) * Nd + n0 + tx];
        __nv_bfloat16 h = __float2bfloat16(v);
        th[ty + 8 * j][tx] = h;
        tl[ty + 8 * j][tx] = __float2bfloat16(v - __bfloat162float(h));
    }
    __syncthreads();
    #pragma unroll
    for (int j = 0; j < 4; j++) {
        hiT[(size_t)(n0 + ty + 8 * j) * Kd + k0 + tx] = th[tx][ty + 8 * j];
        loT[(size_t)(n0 + ty + 8 * j) * Kd + k0 + tx] = tl[tx][ty + 8 * j];
    }
}

// ---------------------------------------------------------------------------
// bf16-split GEMM on HMMA: C[M,N] = A @ B^T + bias.
// A: [M][K] bf16 hi/lo (row-major). B: [N][K] bf16 hi/lo (K-major rows).
// CTA 128x128, 8 warps (2m x 4n), warp 64x32 (4 m16 x 4 n8). K-chunk 32.
// ---------------------------------------------------------------------------
#define AS_LD 40
__global__ void __launch_bounds__(256, 2)
gemm_bf16_kernel(const __nv_bfloat16* __restrict__ Ah, const __nv_bfloat16* __restrict__ Al,
                 const __nv_bfloat16* __restrict__ Bh, const __nv_bfloat16* __restrict__ Bl,
                 const float* __restrict__ bias, float* __restrict__ C,
                 int M, int N, int K) {
    __shared__ __nv_bfloat16 Ash[128 * AS_LD];
    __shared__ __nv_bfloat16 Asl[128 * AS_LD];
    __shared__ __nv_bfloat16 Bsh[128 * AS_LD];
    __shared__ __nv_bfloat16 Bsl[128 * AS_LD];

    const int tid = threadIdx.x;
    const int wid = tid >> 5, lane = tid & 31;
    const int g = lane >> 2, q4 = lane & 3;
    const int wm = wid >> 2, wn = wid & 3;
    const int m0 = blockIdx.y * 128, n0 = blockIdx.x * 128;
    const int lrow = tid >> 1, loff = (tid & 1) * 16;

    float Cf[4][4][4];
    #pragma unroll
    for (int mt = 0; mt < 4; mt++)
        #pragma unroll
        for (int nt = 0; nt < 4; nt++)
            #pragma unroll
            for (int e = 0; e < 4; e++) Cf[mt][nt][e] = 0.0f;

    for (int k0 = 0; k0 < K; k0 += 32) {
        __syncthreads();
        // Each thread loads a full 16-element (32B) half-row per array (2x uint4)
        {
            const __nv_bfloat16* pa = Ah + (size_t)(m0 + lrow) * K + k0 + loff;
            *reinterpret_cast<uint4*>(&Ash[lrow * AS_LD + loff])     = *reinterpret_cast<const uint4*>(pa);
            *reinterpret_cast<uint4*>(&Ash[lrow * AS_LD + loff + 8]) = *reinterpret_cast<const uint4*>(pa + 8);
            const __nv_bfloat16* pl = Al + (size_t)(m0 + lrow) * K + k0 + loff;
            *reinterpret_cast<uint4*>(&Asl[lrow * AS_LD + loff])     = *reinterpret_cast<const uint4*>(pl);
            *reinterpret_cast<uint4*>(&Asl[lrow * AS_LD + loff + 8]) = *reinterpret_cast<const uint4*>(pl + 8);
            const __nv_bfloat16* pb = Bh + (size_t)(n0 + lrow) * K + k0 + loff;
            *reinterpret_cast<uint4*>(&Bsh[lrow * AS_LD + loff])     = *reinterpret_cast<const uint4*>(pb);
            *reinterpret_cast<uint4*>(&Bsh[lrow * AS_LD + loff + 8]) = *reinterpret_cast<const uint4*>(pb + 8);
            const __nv_bfloat16* pc = Bl + (size_t)(n0 + lrow) * K + k0 + loff;
            *reinterpret_cast<uint4*>(&Bsl[lrow * AS_LD + loff])     = *reinterpret_cast<const uint4*>(pc);
            *reinterpret_cast<uint4*>(&Bsl[lrow * AS_LD + loff + 8]) = *reinterpret_cast<const uint4*>(pc + 8);
        }
        __syncthreads();

        #pragma unroll
        for (int ks = 0; ks < 2; ks++) {
            const int kk = ks * 16 + 2 * q4;
            uint32_t bh[4][2], bl[4][2];
            #pragma unroll
            for (int nt = 0; nt < 4; nt++) {
                int nr = (wn * 32 + nt * 8 + g) * AS_LD;
                bh[nt][0] = *reinterpret_cast<uint32_t*>(&Bsh[nr + kk]);
                bh[nt][1] = *reinterpret_cast<uint32_t*>(&Bsh[nr + kk + 8]);
                bl[nt][0] = *reinterpret_cast<uint32_t*>(&Bsl[nr + kk]);
                bl[nt][1] = *reinterpret_cast<uint32_t*>(&Bsl[nr + kk + 8]);
            }
            #pragma unroll
            for (int mt = 0; mt < 4; mt++) {
                int r0 = (wm * 64 + mt * 16 + g) * AS_LD;
                int r1 = r0 + 8 * AS_LD;
                uint32_t ah[4], al[4];
                ah[0] = *reinterpret_cast<uint32_t*>(&Ash[r0 + kk]);
                ah[1] = *reinterpret_cast<uint32_t*>(&Ash[r1 + kk]);
                ah[2] = *reinterpret_cast<uint32_t*>(&Ash[r0 + kk + 8]);
                ah[3] = *reinterpret_cast<uint32_t*>(&Ash[r1 + kk + 8]);
                al[0] = *reinterpret_cast<uint32_t*>(&Asl[r0 + kk]);
                al[1] = *reinterpret_cast<uint32_t*>(&Asl[r1 + kk]);
                al[2] = *reinterpret_cast<uint32_t*>(&Asl[r0 + kk + 8]);
                al[3] = *reinterpret_cast<uint32_t*>(&Asl[r1 + kk + 8]);
                #pragma unroll
                for (int nt = 0; nt < 4; nt++) {
                    mma_bf16(Cf[mt][nt], ah, bh[nt]);
                    mma_bf16(Cf[mt][nt], ah, bl[nt]);
                    mma_bf16(Cf[mt][nt], al, bh[nt]);
                }
            }
        }
    }

    #pragma unroll
    for (int mt = 0; mt < 4; mt++) {
        int row = m0 + wm * 64 + mt * 16 + g;
        #pragma unroll
        for (int nt = 0; nt < 4; nt++) {
            int col = n0 + wn * 32 + nt * 8 + 2 * q4;
            float2 b2 = *reinterpret_cast<const float2*>(bias + col);
            float2 o0 = {Cf[mt][nt][0] + b2.x, Cf[mt][nt][1] + b2.y};
            float2 o1 = {Cf[mt][nt][2] + b2.x, Cf[mt][nt][3] + b2.y};
            *reinterpret_cast<float2*>(C + (size_t)row * N + col) = o0;
            *reinterpret_cast<float2*>(C + (size_t)(row + 8) * N + col) = o1;
        }
    }
}

// ---------------------------------------------------------------------------
// Flash attention on tf32 HMMA. Br=128 (8 warps x 16 rows), Bc=64.
// Warp owns full rows -> softmax reductions within a 4-lane quad.
// ---------------------------------------------------------------------------
#define FQ_LD 68
#define FLASH_SMEM ((128 + 64 + 64 + 128) * FQ_LD * 4)   // 104448 B

__global__ void __launch_bounds__(256)
flash_tf32_kernel(const float* __restrict__ qkv, float* __restrict__ outp) {
    extern __shared__ uint32_t sm[];
    uint32_t* Qs = sm;                      // [128][68] tf32 (pre-scaled)
    uint32_t* Ks = Qs + 128 * FQ_LD;        // [64][68]  (kvrow, d)
    uint32_t* Vs = Ks + 64 * FQ_LD;         // [64][68]  (kvrow, d)
    uint32_t* Ps = Vs + 64 * FQ_LD;         // [8][16][68] per-warp P

    const int qb = (S_LEN / 128 - 1) - blockIdx.x;   // heavy tiles first
    const int h  = blockIdx.y;
    const int tid = threadIdx.x;
    const int wid = tid >> 5, lane = tid & 31;
    const int g = lane >> 2, q4 = lane & 3;
    const int qcol = h * HDIM;
    const float scale = 0.125f;

    #pragma unroll
    for (int i = 0; i < 8; i++) {
        int p = tid + i * 256;
        int r = p >> 4, c4 = (p & 15) * 4;
        float4 q = *reinterpret_cast<const float4*>(
            qkv + (size_t)(qb * 128 + r) * N3 + qcol + c4);
        Qs[r * FQ_LD + c4 + 0] = f2tf32(q.x * scale);
        Qs[r * FQ_LD + c4 + 1] = f2tf32(q.y * scale);
        Qs[r * FQ_LD + c4 + 2] = f2tf32(q.z * scale);
        Qs[r * FQ_LD + c4 + 3] = f2tf32(q.w * scale);
    }

    float O[8][4];
    #pragma unroll
    for (int nt = 0; nt < 8; nt++)
        #pragma unroll
        for (int e = 0; e < 4; e++) O[nt][e] = 0.0f;
    float m0r = -1e30f, m1r = -1e30f, l0r = 0.0f, l1r = 0.0f;

    const uint32_t* Qb = Qs + (wid * 16) * FQ_LD;
    uint32_t* Pw = Ps + (wid * 16) * FQ_LD;

    const int nkt = 2 * qb + 2;
    for (int kb = 0; kb < nkt; kb++) {
        __syncthreads();
        #pragma unroll
        for (int i = 0; i < 4; i++) {
            int p = tid + i * 256;
            int r = p >> 4, c4 = (p & 15) * 4;
            const float* base = qkv + (size_t)(kb * 64 + r) * N3 + DMODEL + qcol;
            float4 k4 = *reinterpret_cast<const float4*>(base + c4);
            Ks[r * FQ_LD + c4 + 0] = f2tf32(k4.x);
            Ks[r * FQ_LD + c4 + 1] = f2tf32(k4.y);
            Ks[r * FQ_LD + c4 + 2] = f2tf32(k4.z);
            Ks[r * FQ_LD + c4 + 3] = f2tf32(k4.w);
            float4 v4 = *reinterpret_cast<const float4*>(base + DMODEL + c4);
            Vs[r * FQ_LD + c4 + 0] = f2tf32(v4.x);
            Vs[r * FQ_LD + c4 + 1] = f2tf32(v4.y);
            Vs[r * FQ_LD + c4 + 2] = f2tf32(v4.z);
            Vs[r * FQ_LD + c4 + 3] = f2tf32(v4.w);
        }
        __syncthreads();

        // S = Q K^T  (warp: 16 x 64, tf32 m16n8k8)
        float S[8][4];
        #pragma unroll
        for (int nt = 0; nt < 8; nt++)
            #pragma unroll
            for (int e = 0; e < 4; e++) S[nt][e] = 0.0f;

        #pragma unroll
        for (int ks = 0; ks < 8; ks++) {
            const int kk = ks * 8 + q4;
            uint32_t a[4];
            a[0] = Qb[g * FQ_LD + kk];
            a[1] = Qb[(g + 8) * FQ_LD + kk];
            a[2] = Qb[g * FQ_LD + kk + 4];
            a[3] = Qb[(g + 8) * FQ_LD + kk + 4];
            #pragma unroll
            for (int nt = 0; nt < 8; nt++) {
                uint32_t b[2];
                b[0] = Ks[(nt * 8 + g) * FQ_LD + kk];
                b[1] = Ks[(nt * 8 + g) * FQ_LD + kk + 4];
                mma_tf32(S[nt], a, b);
            }
        }

        // Causal mask (diagonal tiles only)
        if (kb >= 2 * qb) {
            int row0 = qb * 128 + wid * 16 + g;
            int row1 = row0 + 8;
            #pragma unroll
            for (int nt = 0; nt < 8; nt++) {
                int c = kb * 64 + nt * 8 + 2 * q4;
                if (c     > row0) S[nt][0] = -1e30f;
                if (c + 1 > row0) S[nt][1] = -1e30f;
                if (c     > row1) S[nt][2] = -1e30f;
                if (c + 1 > row1) S[nt][3] = -1e30f;
            }
        }

        // Online softmax (rows g, g+8 of the warp band; quad shfl reduce)
        float mx0 = -1e30f, mx1 = -1e30f;
        #pragma unroll
        for (int nt = 0; nt < 8; nt++) {
            mx0 = fmaxf(mx0, fmaxf(S[nt][0], S[nt][1]));
            mx1 = fmaxf(mx1, fmaxf(S[nt][2], S[nt][3]));
        }
        mx0 = fmaxf(mx0, __shfl_xor_sync(0xffffffffu, mx0, 1));
        mx0 = fmaxf(mx0, __shfl_xor_sync(0xffffffffu, mx0, 2));
        mx1 = fmaxf(mx1, __shfl_xor_sync(0xffffffffu, mx1, 1));
        mx1 = fmaxf(mx1, __shfl_xor_sync(0xffffffffu, mx1, 2));
        float mn0 = fmaxf(m0r, mx0), mn1 = fmaxf(m1r, mx1);
        float al0 = __expf(m0r - mn0), al1 = __expf(m1r - mn1);
        float rs0 = 0.0f, rs1 = 0.0f;
        #pragma unroll
        for (int nt = 0; nt < 8; nt++) {
            float p0 = __expf(S[nt][0] - mn0);
            float p1 = __expf(S[nt][1] - mn0);
            float p2 = __expf(S[nt][2] - mn1);
            float p3 = __expf(S[nt][3] - mn1);
            rs0 += p0 + p1;
            rs1 += p2 + p3;
            int c = nt * 8 + 2 * q4;
            Pw[g * FQ_LD + c]           = f2tf32(p0);
            Pw[g * FQ_LD + c + 1]       = f2tf32(p1);
            Pw[(g + 8) * FQ_LD + c]     = f2tf32(p2);
            Pw[(g + 8) * FQ_LD + c + 1] = f2tf32(p3);
        }
        rs0 += __shfl_xor_sync(0xffffffffu, rs0, 1);
        rs0 += __shfl_xor_sync(0xffffffffu, rs0, 2);
        rs1 += __shfl_xor_sync(0xffffffffu, rs1, 1);
        rs1 += __shfl_xor_sync(0xffffffffu, rs1, 2);
        l0r = l0r * al0 + rs0;
        l1r = l1r * al1 + rs1;
        m0r = mn0; m1r = mn1;
        #pragma unroll
        for (int nt = 0; nt < 8; nt++) {
            O[nt][0] *= al0; O[nt][1] *= al0;
            O[nt][2] *= al1; O[nt][3] *= al1;
        }
        __syncwarp();

        // O += P @ V
        #pragma unroll
        for (int ks = 0; ks < 8; ks++) {
            const int kk = ks * 8 + q4;
            uint32_t a[4];
            a[0] = Pw[g * FQ_LD + kk];
            a[1] = Pw[(g + 8) * FQ_LD + kk];
            a[2] = Pw[g * FQ_LD + kk + 4];
            a[3] = Pw[(g + 8) * FQ_LD + kk + 4];
            #pragma unroll
            for (int nt = 0; nt < 8; nt++) {
                uint32_t b[2];
                b[0] = Vs[kk * FQ_LD + nt * 8 + g];
                b[1] = Vs[(kk + 4) * FQ_LD + nt * 8 + g];
                mma_tf32(O[nt], a, b);
            }
        }
    }

    // Epilogue
    float inv0 = 1.0f / l0r, inv1 = 1.0f / l1r;
    int row0 = qb * 128 + wid * 16 + g;
    int row1 = row0 + 8;
    #pragma unroll
    for (int nt = 0; nt < 8; nt++) {
        int col = qcol + nt * 8 + 2 * q4;
        float2 o0 = {O[nt][0] * inv0, O[nt][1] * inv0};
        float2 o1 = {O[nt][2] * inv1, O[nt][3] * inv1};
        *reinterpret_cast<float2*>(outp + (size_t)row0 * DMODEL + col) = o0;
        *reinterpret_cast<float2*>(outp + (size_t)row1 * DMODEL + col) = o1;
    }
}

// ---------------------------------------------------------------------------
// Launch
// ---------------------------------------------------------------------------
extern "C" void kernel_launch(void* const* d_in, const int* in_sizes, int n_in,
                              void* d_out, int out_size) {
    const float* x      = (const float*)d_in[0];
    const float* w_qkv  = (const float*)d_in[1];
    const float* b_qkv  = (const float*)d_in[2];
    const float* w_proj = (const float*)d_in[3];
    const float* b_proj = (const float*)d_in[4];
    float* out = (float*)d_out;

    float *qkv, *attn;
    __nv_bfloat16 *xhi, *xlo, *ahi, *alo, *wqh, *wql, *wph, *wpl;
    cudaGetSymbolAddress((void**)&qkv, g_qkv);
    cudaGetSymbolAddress((void**)&attn, g_attn);
    cudaGetSymbolAddress((void**)&xhi, g_xhi);
    cudaGetSymbolAddress((void**)&xlo, g_xlo);
    cudaGetSymbolAddress((void**)&ahi, g_ahi);
    cudaGetSymbolAddress((void**)&alo, g_alo);
    cudaGetSymbolAddress((void**)&wqh, g_wqh);
    cudaGetSymbolAddress((void**)&wql, g_wql);
    cudaGetSymbolAddress((void**)&wph, g_wph);
    cudaGetSymbolAddress((void**)&wpl, g_wpl);

    cudaFuncSetAttribute(flash_tf32_kernel,
                         cudaFuncAttributeMaxDynamicSharedMemorySize, FLASH_SMEM);

    // Prep: split x; split+transpose weights
    split_kernel<<<S_LEN * DMODEL / 1024, 256>>>(x, xhi, xlo);
    splitT_kernel<<<dim3(N3 / 32, DMODEL / 32), dim3(32, 8)>>>(w_qkv, wqh, wql, DMODEL, N3);
    splitT_kernel<<<dim3(DMODEL / 32, DMODEL / 32), dim3(32, 8)>>>(w_proj, wph, wpl, DMODEL, DMODEL);

    // 1) QKV projection
    gemm_bf16_kernel<<<dim3(N3 / 128, S_LEN / 128), 256>>>(
        xhi, xlo, wqh, wql, b_qkv, qkv, S_LEN, N3, DMODEL);

    // 2) Causal flash attention (tf32 HMMA)
    flash_tf32_kernel<<<dim3(S_LEN / 128, NHEAD), 256, FLASH_SMEM>>>(qkv, attn);

    // 3) Output projection
    split_kernel<<<S_LEN * DMODEL / 1024, 256>>>(attn, ahi, alo);
    gemm_bf16_kernel<<<dim3(DMODEL / 128, S_LEN / 128), 256>>>(
        ahi, alo, wph, wpl, b_proj, out, S_LEN, DMODEL, DMODEL);
}

// round 8
// speedup vs baseline: 2.6487x; 1.0813x over previous
#include <cuda_runtime.h>
#include <cuda_bf16.h>
#include <cstdint>

// Problem constants
#define S_LEN   4096
#define DMODEL  1024
#define NHEAD   16
#define HDIM    64
#define N3      3072

// Scratch (__device__ globals per allocation-free rule)
__device__ float g_qkv[S_LEN * N3];
__device__ float g_attn[S_LEN * DMODEL];
__device__ __nv_bfloat16 g_xhi[S_LEN * DMODEL], g_xlo[S_LEN * DMODEL];
__device__ __nv_bfloat16 g_ahi[S_LEN * DMODEL], g_alo[S_LEN * DMODEL];
__device__ __nv_bfloat16 g_wqh[N3 * DMODEL],   g_wql[N3 * DMODEL];
__device__ __nv_bfloat16 g_wph[DMODEL * DMODEL], g_wpl[DMODEL * DMODEL];

// ---------------------------------------------------------------------------
// PTX helpers
// ---------------------------------------------------------------------------
__device__ __forceinline__ uint32_t smem_u32(const void* p) {
    uint32_t a;
    asm("{ .reg .u64 t; cvta.to.shared.u64 t, %1; cvt.u32.u64 %0, t; }"
        : "=r"(a) : "l"(p));
    return a;
}

__device__ __forceinline__ void mma_bf16(float* c, const uint32_t* a, const uint32_t* b) {
    asm volatile(
        "mma.sync.aligned.m16n8k16.row.col.f32.bf16.bf16.f32 "
        "{%0,%1,%2,%3}, {%4,%5,%6,%7}, {%8,%9}, {%0,%1,%2,%3};"
        : "+f"(c[0]), "+f"(c[1]), "+f"(c[2]), "+f"(c[3])
        : "r"(a[0]), "r"(a[1]), "r"(a[2]), "r"(a[3]), "r"(b[0]), "r"(b[1]));
}

__device__ __forceinline__ void mma_tf32(float* c, const uint32_t* a, const uint32_t* b) {
    asm volatile(
        "mma.sync.aligned.m16n8k8.row.col.f32.tf32.tf32.f32 "
        "{%0,%1,%2,%3}, {%4,%5,%6,%7}, {%8,%9}, {%0,%1,%2,%3};"
        : "+f"(c[0]), "+f"(c[1]), "+f"(c[2]), "+f"(c[3])
        : "r"(a[0]), "r"(a[1]), "r"(a[2]), "r"(a[3]), "r"(b[0]), "r"(b[1]));
}

__device__ __forceinline__ uint32_t f2tf32(float x) {
    uint32_t r;
    asm("cvt.rna.tf32.f32 %0, %1;" : "=r"(r) : "f"(x));
    return r;
}

__device__ __forceinline__ void ldm_x4(uint32_t* r, uint32_t saddr) {
    asm volatile("ldmatrix.sync.aligned.m8n8.x4.shared.b16 {%0,%1,%2,%3}, [%4];"
                 : "=r"(r[0]), "=r"(r[1]), "=r"(r[2]), "=r"(r[3]) : "r"(saddr));
}

// ---------------------------------------------------------------------------
// Prep kernels (unchanged, validated in R5)
// ---------------------------------------------------------------------------
__global__ void __launch_bounds__(256)
split_kernel(const float* __restrict__ in,
             __nv_bfloat16* __restrict__ hi, __nv_bfloat16* __restrict__ lo) {
    int i = (blockIdx.x * 256 + threadIdx.x) * 4;
    float4 v = *reinterpret_cast<const float4*>(in + i);
    __nv_bfloat16 h0 = __float2bfloat16(v.x), h1 = __float2bfloat16(v.y);
    __nv_bfloat16 h2 = __float2bfloat16(v.z), h3 = __float2bfloat16(v.w);
    __nv_bfloat162 ha; ha.x = h0; ha.y = h1;
    __nv_bfloat162 hb; hb.x = h2; hb.y = h3;
    __nv_bfloat162 la;
    la.x = __float2bfloat16(v.x - __bfloat162float(h0));
    la.y = __float2bfloat16(v.y - __bfloat162float(h1));
    __nv_bfloat162 lb;
    lb.x = __float2bfloat16(v.z - __bfloat162float(h2));
    lb.y = __float2bfloat16(v.w - __bfloat162float(h3));
    *reinterpret_cast<__nv_bfloat162*>(hi + i)     = ha;
    *reinterpret_cast<__nv_bfloat162*>(hi + i + 2) = hb;
    *reinterpret_cast<__nv_bfloat162*>(lo + i)     = la;
    *reinterpret_cast<__nv_bfloat162*>(lo + i + 2) = lb;
}

__global__ void __launch_bounds__(256)
splitT_kernel(const float* __restrict__ W,
              __nv_bfloat16* __restrict__ hiT, __nv_bfloat16* __restrict__ loT,
              int Kd, int Nd) {
    __shared__ __nv_bfloat16 th[32][33];
    __shared__ __nv_bfloat16 tl[32][33];
    int n0 = blockIdx.x * 32, k0 = blockIdx.y * 32;
    int tx = threadIdx.x, ty = threadIdx.y;
    #pragma unroll
    for (int j = 0; j < 4; j++) {
        float v = W[(size_t)(k0 + ty + 8 * j) * Nd + n0 + tx];
        __nv_bfloat16 h = __float2bfloat16(v);
        th[ty + 8 * j][tx] = h;
        tl[ty + 8 * j][tx] = __float2bfloat16(v - __bfloat162float(h));
    }
    __syncthreads();
    #pragma unroll
    for (int j = 0; j < 4; j++) {
        hiT[(size_t)(n0 + ty + 8 * j) * Kd + k0 + tx] = th[tx][ty + 8 * j];
        loT[(size_t)(n0 + ty + 8 * j) * Kd + k0 + tx] = tl[tx][ty + 8 * j];
    }
}

// ---------------------------------------------------------------------------
// bf16-split GEMM on HMMA: C[M,N] = A @ B^T + bias.
// R5 skeleton (static smem, sync uint4 loads) + ldmatrix fragment loads.
// CTA 128x128, K-chunk 32, 8 warps (2m x 4n).
// ---------------------------------------------------------------------------
#define AS_LD 40
__global__ void __launch_bounds__(256, 2)
gemm_bf16_kernel(const __nv_bfloat16* __restrict__ Ah, const __nv_bfloat16* __restrict__ Al,
                 const __nv_bfloat16* __restrict__ Bh, const __nv_bfloat16* __restrict__ Bl,
                 const float* __restrict__ bias, float* __restrict__ C,
                 int M, int N, int K) {
    __shared__ __nv_bfloat16 Ash[128 * AS_LD];
    __shared__ __nv_bfloat16 Asl[128 * AS_LD];
    __shared__ __nv_bfloat16 Bsh[128 * AS_LD];
    __shared__ __nv_bfloat16 Bsl[128 * AS_LD];

    const int tid = threadIdx.x;
    const int wid = tid >> 5, lane = tid & 31;
    const int g = lane >> 2, q4 = lane & 3;
    const int wm = wid >> 2, wn = wid & 3;
    const int m0 = blockIdx.y * 128, n0 = blockIdx.x * 128;
    const int lrow = tid >> 1, loff = (tid & 1) * 16;

    // ldmatrix per-lane byte offsets (validated against R5 scalar pattern):
    // A x4: lanes 0-7 rows+0-7 k+0 | 8-15 rows+8-15 k+0 | 16-23 rows+0-7 k+8 | 24-31 rows+8-15 k+8
    const uint32_t a_off2 = (uint32_t)(((wm * 64) + ((lane >> 3) & 1) * 8 + (lane & 7)) * AS_LD
                                       + (lane >> 4) * 8) * 2;
    // B x4: lanes 0-7 n+0-7 k+0 | 8-15 n+0-7 k+8 | 16-23 n+8-15 k+0 | 24-31 n+8-15 k+8
    const uint32_t b_off2 = (uint32_t)(((wn * 32) + (lane >> 4) * 8 + (lane & 7)) * AS_LD
                                       + ((lane >> 3) & 1) * 8) * 2;

    const uint32_t sAh = smem_u32(Ash) + a_off2;
    const uint32_t sAl = smem_u32(Asl) + a_off2;
    const uint32_t sBh = smem_u32(Bsh) + b_off2;
    const uint32_t sBl = smem_u32(Bsl) + b_off2;

    float Cf[4][4][4];
    #pragma unroll
    for (int mt = 0; mt < 4; mt++)
        #pragma unroll
        for (int nt = 0; nt < 4; nt++)
            #pragma unroll
            for (int e = 0; e < 4; e++) Cf[mt][nt][e] = 0.0f;

    for (int k0 = 0; k0 < K; k0 += 32) {
        __syncthreads();
        // Each thread loads a full 16-element (32B) half-row per array (2x uint4)
        {
            const __nv_bfloat16* pa = Ah + (size_t)(m0 + lrow) * K + k0 + loff;
            *reinterpret_cast<uint4*>(&Ash[lrow * AS_LD + loff])     = *reinterpret_cast<const uint4*>(pa);
            *reinterpret_cast<uint4*>(&Ash[lrow * AS_LD + loff + 8]) = *reinterpret_cast<const uint4*>(pa + 8);
            const __nv_bfloat16* pl = Al + (size_t)(m0 + lrow) * K + k0 + loff;
            *reinterpret_cast<uint4*>(&Asl[lrow * AS_LD + loff])     = *reinterpret_cast<const uint4*>(pl);
            *reinterpret_cast<uint4*>(&Asl[lrow * AS_LD + loff + 8]) = *reinterpret_cast<const uint4*>(pl + 8);
            const __nv_bfloat16* pb = Bh + (size_t)(n0 + lrow) * K + k0 + loff;
            *reinterpret_cast<uint4*>(&Bsh[lrow * AS_LD + loff])     = *reinterpret_cast<const uint4*>(pb);
            *reinterpret_cast<uint4*>(&Bsh[lrow * AS_LD + loff + 8]) = *reinterpret_cast<const uint4*>(pb + 8);
            const __nv_bfloat16* pc = Bl + (size_t)(n0 + lrow) * K + k0 + loff;
            *reinterpret_cast<uint4*>(&Bsl[lrow * AS_LD + loff])     = *reinterpret_cast<const uint4*>(pc);
            *reinterpret_cast<uint4*>(&Bsl[lrow * AS_LD + loff + 8]) = *reinterpret_cast<const uint4*>(pc + 8);
        }
        __syncthreads();

        #pragma unroll
        for (int ks = 0; ks < 2; ks++) {
            uint32_t bh4[2][4], bl4[2][4];
            #pragma unroll
            for (int ntp = 0; ntp < 2; ntp++) {
                ldm_x4(bh4[ntp], sBh + ntp * 1280 + ks * 32);   // 16 rows * 40 * 2 = 1280 B
                ldm_x4(bl4[ntp], sBl + ntp * 1280 + ks * 32);
            }
            #pragma unroll
            for (int mt = 0; mt < 4; mt++) {
                uint32_t ah4[4], al4[4];
                ldm_x4(ah4, sAh + mt * 1280 + ks * 32);
                ldm_x4(al4, sAl + mt * 1280 + ks * 32);
                #pragma unroll
                for (int ntp = 0; ntp < 2; ntp++) {
                    mma_bf16(Cf[mt][2 * ntp],     ah4, &bh4[ntp][0]);
                    mma_bf16(Cf[mt][2 * ntp],     ah4, &bl4[ntp][0]);
                    mma_bf16(Cf[mt][2 * ntp],     al4, &bh4[ntp][0]);
                    mma_bf16(Cf[mt][2 * ntp + 1], ah4, &bh4[ntp][2]);
                    mma_bf16(Cf[mt][2 * ntp + 1], ah4, &bl4[ntp][2]);
                    mma_bf16(Cf[mt][2 * ntp + 1], al4, &bh4[ntp][2]);
                }
            }
        }
    }

    // Epilogue (R5-identical): direct float2 stores
    #pragma unroll
    for (int mt = 0; mt < 4; mt++) {
        int row = m0 + wm * 64 + mt * 16 + g;
        #pragma unroll
        for (int nt = 0; nt < 4; nt++) {
            int col = n0 + wn * 32 + nt * 8 + 2 * q4;
            float2 b2 = *reinterpret_cast<const float2*>(bias + col);
            float2 o0 = {Cf[mt][nt][0] + b2.x, Cf[mt][nt][1] + b2.y};
            float2 o1 = {Cf[mt][nt][2] + b2.x, Cf[mt][nt][3] + b2.y};
            *reinterpret_cast<float2*>(C + (size_t)row * N + col) = o0;
            *reinterpret_cast<float2*>(C + (size_t)(row + 8) * N + col) = o1;
        }
    }
}

// ---------------------------------------------------------------------------
// Flash attention on tf32 HMMA — byte-identical to the validated R5 kernel.
// ---------------------------------------------------------------------------
#define FQ_LD 68
#define FLASH_SMEM ((128 + 64 + 64 + 128) * FQ_LD * 4)   // 104448 B

__global__ void __launch_bounds__(256)
flash_tf32_kernel(const float* __restrict__ qkv, float* __restrict__ outp) {
    extern __shared__ uint32_t sm[];
    uint32_t* Qs = sm;                      // [128][68] tf32 (pre-scaled)
    uint32_t* Ks = Qs + 128 * FQ_LD;        // [64][68]  (kvrow, d)
    uint32_t* Vs = Ks + 64 * FQ_LD;         // [64][68]  (kvrow, d)
    uint32_t* Ps = Vs + 64 * FQ_LD;         // [8][16][68] per-warp P

    const int qb = (S_LEN / 128 - 1) - blockIdx.x;   // heavy tiles first
    const int h  = blockIdx.y;
    const int tid = threadIdx.x;
    const int wid = tid >> 5, lane = tid & 31;
    const int g = lane >> 2, q4 = lane & 3;
    const int qcol = h * HDIM;
    const float scale = 0.125f;

    #pragma unroll
    for (int i = 0; i < 8; i++) {
        int p = tid + i * 256;
        int r = p >> 4, c4 = (p & 15) * 4;
        float4 q = *reinterpret_cast<const float4*>(
            qkv + (size_t)(qb * 128 + r) * N3 + qcol + c4);
        Qs[r * FQ_LD + c4 + 0] = f2tf32(q.x * scale);
        Qs[r * FQ_LD + c4 + 1] = f2tf32(q.y * scale);
        Qs[r * FQ_LD + c4 + 2] = f2tf32(q.z * scale);
        Qs[r * FQ_LD + c4 + 3] = f2tf32(q.w * scale);
    }

    float O[8][4];
    #pragma unroll
    for (int nt = 0; nt < 8; nt++)
        #pragma unroll
        for (int e = 0; e < 4; e++) O[nt][e] = 0.0f;
    float m0r = -1e30f, m1r = -1e30f, l0r = 0.0f, l1r = 0.0f;

    const uint32_t* Qb = Qs + (wid * 16) * FQ_LD;
    uint32_t* Pw = Ps + (wid * 16) * FQ_LD;

    const int nkt = 2 * qb + 2;
    for (int kb = 0; kb < nkt; kb++) {
        __syncthreads();
        #pragma unroll
        for (int i = 0; i < 4; i++) {
            int p = tid + i * 256;
            int r = p >> 4, c4 = (p & 15) * 4;
            const float* base = qkv + (size_t)(kb * 64 + r) * N3 + DMODEL + qcol;
            float4 k4 = *reinterpret_cast<const float4*>(base + c4);
            Ks[r * FQ_LD + c4 + 0] = f2tf32(k4.x);
            Ks[r * FQ_LD + c4 + 1] = f2tf32(k4.y);
            Ks[r * FQ_LD + c4 + 2] = f2tf32(k4.z);
            Ks[r * FQ_LD + c4 + 3] = f2tf32(k4.w);
            float4 v4 = *reinterpret_cast<const float4*>(base + DMODEL + c4);
            Vs[r * FQ_LD + c4 + 0] = f2tf32(v4.x);
            Vs[r * FQ_LD + c4 + 1] = f2tf32(v4.y);
            Vs[r * FQ_LD + c4 + 2] = f2tf32(v4.z);
            Vs[r * FQ_LD + c4 + 3] = f2tf32(v4.w);
        }
        __syncthreads();

        float S[8][4];
        #pragma unroll
        for (int nt = 0; nt < 8; nt++)
            #pragma unroll
            for (int e = 0; e < 4; e++) S[nt][e] = 0.0f;

        #pragma unroll
        for (int ks = 0; ks < 8; ks++) {
            const int kk = ks * 8 + q4;
            uint32_t a[4];
            a[0] = Qb[g * FQ_LD + kk];
            a[1] = Qb[(g + 8) * FQ_LD + kk];
            a[2] = Qb[g * FQ_LD + kk + 4];
            a[3] = Qb[(g + 8) * FQ_LD + kk + 4];
            #pragma unroll
            for (int nt = 0; nt < 8; nt++) {
                uint32_t b[2];
                b[0] = Ks[(nt * 8 + g) * FQ_LD + kk];
                b[1] = Ks[(nt * 8 + g) * FQ_LD + kk + 4];
                mma_tf32(S[nt], a, b);
            }
        }

        if (kb >= 2 * qb) {
            int row0 = qb * 128 + wid * 16 + g;
            int row1 = row0 + 8;
            #pragma unroll
            for (int nt = 0; nt < 8; nt++) {
                int c = kb * 64 + nt * 8 + 2 * q4;
                if (c     > row0) S[nt][0] = -1e30f;
                if (c + 1 > row0) S[nt][1] = -1e30f;
                if (c     > row1) S[nt][2] = -1e30f;
                if (c + 1 > row1) S[nt][3] = -1e30f;
            }
        }

        float mx0 = -1e30f, mx1 = -1e30f;
        #pragma unroll
        for (int nt = 0; nt < 8; nt++) {
            mx0 = fmaxf(mx0, fmaxf(S[nt][0], S[nt][1]));
            mx1 = fmaxf(mx1, fmaxf(S[nt][2], S[nt][3]));
        }
        mx0 = fmaxf(mx0, __shfl_xor_sync(0xffffffffu, mx0, 1));
        mx0 = fmaxf(mx0, __shfl_xor_sync(0xffffffffu, mx0, 2));
        mx1 = fmaxf(mx1, __shfl_xor_sync(0xffffffffu, mx1, 1));
        mx1 = fmaxf(mx1, __shfl_xor_sync(0xffffffffu, mx1, 2));
        float mn0 = fmaxf(m0r, mx0), mn1 = fmaxf(m1r, mx1);
        float al0 = __expf(m0r - mn0), al1 = __expf(m1r - mn1);
        float rs0 = 0.0f, rs1 = 0.0f;
        #pragma unroll
        for (int nt = 0; nt < 8; nt++) {
            float p0 = __expf(S[nt][0] - mn0);
            float p1 = __expf(S[nt][1] - mn0);
            float p2 = __expf(S[nt][2] - mn1);
            float p3 = __expf(S[nt][3] - mn1);
            rs0 += p0 + p1;
            rs1 += p2 + p3;
            int c = nt * 8 + 2 * q4;
            Pw[g * FQ_LD + c]           = f2tf32(p0);
            Pw[g * FQ_LD + c + 1]       = f2tf32(p1);
            Pw[(g + 8) * FQ_LD + c]     = f2tf32(p2);
            Pw[(g + 8) * FQ_LD + c + 1] = f2tf32(p3);
        }
        rs0 += __shfl_xor_sync(0xffffffffu, rs0, 1);
        rs0 += __shfl_xor_sync(0xffffffffu, rs0, 2);
        rs1 += __shfl_xor_sync(0xffffffffu, rs1, 1);
        rs1 += __shfl_xor_sync(0xffffffffu, rs1, 2);
        l0r = l0r * al0 + rs0;
        l1r = l1r * al1 + rs1;
        m0r = mn0; m1r = mn1;
        #pragma unroll
        for (int nt = 0; nt < 8; nt++) {
            O[nt][0] *= al0; O[nt][1] *= al0;
            O[nt][2] *= al1; O[nt][3] *= al1;
        }
        __syncwarp();

        #pragma unroll
        for (int ks = 0; ks < 8; ks++) {
            const int kk = ks * 8 + q4;
            uint32_t a[4];
            a[0] = Pw[g * FQ_LD + kk];
            a[1] = Pw[(g + 8) * FQ_LD + kk];
            a[2] = Pw[g * FQ_LD + kk + 4];
            a[3] = Pw[(g + 8) * FQ_LD + kk + 4];
            #pragma unroll
            for (int nt = 0; nt < 8; nt++) {
                uint32_t b[2];
                b[0] = Vs[kk * FQ_LD + nt * 8 + g];
                b[1] = Vs[(kk + 4) * FQ_LD + nt * 8 + g];
                mma_tf32(O[nt], a, b);
            }
        }
    }

    float inv0 = 1.0f / l0r, inv1 = 1.0f / l1r;
    int row0 = qb * 128 + wid * 16 + g;
    int row1 = row0 + 8;
    #pragma unroll
    for (int nt = 0; nt < 8; nt++) {
        int col = qcol + nt * 8 + 2 * q4;
        float2 o0 = {O[nt][0] * inv0, O[nt][1] * inv0};
        float2 o1 = {O[nt][2] * inv1, O[nt][3] * inv1};
        *reinterpret_cast<float2*>(outp + (size_t)row0 * DMODEL + col) = o0;
        *reinterpret_cast<float2*>(outp + (size_t)row1 * DMODEL + col) = o1;
    }
}

// ---------------------------------------------------------------------------
// Launch
// ---------------------------------------------------------------------------
extern "C" void kernel_launch(void* const* d_in, const int* in_sizes, int n_in,
                              void* d_out, int out_size) {
    const float* x      = (const float*)d_in[0];
    const float* w_qkv  = (const float*)d_in[1];
    const float* b_qkv  = (const float*)d_in[2];
    const float* w_proj = (const float*)d_in[3];
    const float* b_proj = (const float*)d_in[4];
    float* out = (float*)d_out;

    float *qkv, *attn;
    __nv_bfloat16 *xhi, *xlo, *ahi, *alo, *wqh, *wql, *wph, *wpl;
    cudaGetSymbolAddress((void**)&qkv, g_qkv);
    cudaGetSymbolAddress((void**)&attn, g_attn);
    cudaGetSymbolAddress((void**)&xhi, g_xhi);
    cudaGetSymbolAddress((void**)&xlo, g_xlo);
    cudaGetSymbolAddress((void**)&ahi, g_ahi);
    cudaGetSymbolAddress((void**)&alo, g_alo);
    cudaGetSymbolAddress((void**)&wqh, g_wqh);
    cudaGetSymbolAddress((void**)&wql, g_wql);
    cudaGetSymbolAddress((void**)&wph, g_wph);
    cudaGetSymbolAddress((void**)&wpl, g_wpl);

    cudaFuncSetAttribute(flash_tf32_kernel,
                         cudaFuncAttributeMaxDynamicSharedMemorySize, FLASH_SMEM);

    // Prep: split x; split+transpose weights
    split_kernel<<<S_LEN * DMODEL / 1024, 256>>>(x, xhi, xlo);
    splitT_kernel<<<dim3(N3 / 32, DMODEL / 32), dim3(32, 8)>>>(w_qkv, wqh, wql, DMODEL, N3);
    splitT_kernel<<<dim3(DMODEL / 32, DMODEL / 32), dim3(32, 8)>>>(w_proj, wph, wpl, DMODEL, DMODEL);

    // 1) QKV projection
    gemm_bf16_kernel<<<dim3(N3 / 128, S_LEN / 128), 256>>>(
        xhi, xlo, wqh, wql, b_qkv, qkv, S_LEN, N3, DMODEL);

    // 2) Causal flash attention (R5 tf32 kernel, unchanged)
    flash_tf32_kernel<<<dim3(S_LEN / 128, NHEAD), 256, FLASH_SMEM>>>(qkv, attn);

    // 3) Output projection
    split_kernel<<<S_LEN * DMODEL / 1024, 256>>>(attn, ahi, alo);
    gemm_bf16_kernel<<<dim3(DMODEL / 128, S_LEN / 128), 256>>>(
        ahi, alo, wph, wpl, b_proj, out, S_LEN, DMODEL, DMODEL);
}

// round 9
// speedup vs baseline: 2.8385x; 1.0717x over previous
#include <cuda_runtime.h>
#include <cuda_bf16.h>
#include <cstdint>

// Problem constants
#define S_LEN   4096
#define DMODEL  1024
#define NHEAD   16
#define HDIM    64
#define N3      3072

// Scratch (__device__ globals per allocation-free rule)
__device__ float g_qkv[S_LEN * N3];
__device__ float g_attn[S_LEN * DMODEL];
__device__ __nv_bfloat16 g_xhi[S_LEN * DMODEL], g_xlo[S_LEN * DMODEL];
__device__ __nv_bfloat16 g_ahi[S_LEN * DMODEL], g_alo[S_LEN * DMODEL];
__device__ __nv_bfloat16 g_wqh[N3 * DMODEL],   g_wql[N3 * DMODEL];
__device__ __nv_bfloat16 g_wph[DMODEL * DMODEL], g_wpl[DMODEL * DMODEL];

// ---------------------------------------------------------------------------
// PTX helpers
// ---------------------------------------------------------------------------
__device__ __forceinline__ uint32_t smem_u32(const void* p) {
    uint32_t a;
    asm("{ .reg .u64 t; cvta.to.shared.u64 t, %1; cvt.u32.u64 %0, t; }"
        : "=r"(a) : "l"(p));
    return a;
}

__device__ __forceinline__ void mma_bf16(float* c, const uint32_t* a, const uint32_t* b) {
    asm volatile(
        "mma.sync.aligned.m16n8k16.row.col.f32.bf16.bf16.f32 "
        "{%0,%1,%2,%3}, {%4,%5,%6,%7}, {%8,%9}, {%0,%1,%2,%3};"
        : "+f"(c[0]), "+f"(c[1]), "+f"(c[2]), "+f"(c[3])
        : "r"(a[0]), "r"(a[1]), "r"(a[2]), "r"(a[3]), "r"(b[0]), "r"(b[1]));
}

__device__ __forceinline__ void ldm_x4(uint32_t* r, uint32_t saddr) {
    asm volatile("ldmatrix.sync.aligned.m8n8.x4.shared.b16 {%0,%1,%2,%3}, [%4];"
                 : "=r"(r[0]), "=r"(r[1]), "=r"(r[2]), "=r"(r[3]) : "r"(saddr));
}
__device__ __forceinline__ void ldm_x4_t(uint32_t* r, uint32_t saddr) {
    asm volatile("ldmatrix.sync.aligned.m8n8.x4.trans.shared.b16 {%0,%1,%2,%3}, [%4];"
                 : "=r"(r[0]), "=r"(r[1]), "=r"(r[2]), "=r"(r[3]) : "r"(saddr));
}

// pack two fp32 into bf16x2 hi + residual lo
__device__ __forceinline__ void pack_pair(float p0, float p1, uint32_t& hi, uint32_t& lo) {
    __nv_bfloat162 h;
    h.x = __float2bfloat16(p0);
    h.y = __float2bfloat16(p1);
    hi = *reinterpret_cast<uint32_t*>(&h);
    __nv_bfloat162 l;
    l.x = __float2bfloat16(p0 - __bfloat162float(h.x));
    l.y = __float2bfloat16(p1 - __bfloat162float(h.y));
    lo = *reinterpret_cast<uint32_t*>(&l);
}

// split fp32x4 -> hi/lo bf16x2 pairs at smem base+idx (idx multiple of 4)
__device__ __forceinline__ void split_store4(__nv_bfloat16* bh, __nv_bfloat16* bl,
                                             int idx, float4 v) {
    __nv_bfloat162 h0; h0.x = __float2bfloat16(v.x); h0.y = __float2bfloat16(v.y);
    __nv_bfloat162 h1; h1.x = __float2bfloat16(v.z); h1.y = __float2bfloat16(v.w);
    __nv_bfloat162 l0;
    l0.x = __float2bfloat16(v.x - __bfloat162float(h0.x));
    l0.y = __float2bfloat16(v.y - __bfloat162float(h0.y));
    __nv_bfloat162 l1;
    l1.x = __float2bfloat16(v.z - __bfloat162float(h1.x));
    l1.y = __float2bfloat16(v.w - __bfloat162float(h1.y));
    *reinterpret_cast<__nv_bfloat162*>(bh + idx)     = h0;
    *reinterpret_cast<__nv_bfloat162*>(bh + idx + 2) = h1;
    *reinterpret_cast<__nv_bfloat162*>(bl + idx)     = l0;
    *reinterpret_cast<__nv_bfloat162*>(bl + idx + 2) = l1;
}

// ---------------------------------------------------------------------------
// Prep kernels (unchanged, validated)
// ---------------------------------------------------------------------------
__global__ void __launch_bounds__(256)
split_kernel(const float* __restrict__ in,
             __nv_bfloat16* __restrict__ hi, __nv_bfloat16* __restrict__ lo) {
    int i = (blockIdx.x * 256 + threadIdx.x) * 4;
    float4 v = *reinterpret_cast<const float4*>(in + i);
    split_store4(hi, lo, i, v);
}

__global__ void __launch_bounds__(256)
splitT_kernel(const float* __restrict__ W,
              __nv_bfloat16* __restrict__ hiT, __nv_bfloat16* __restrict__ loT,
              int Kd, int Nd) {
    __shared__ __nv_bfloat16 th[32][33];
    __shared__ __nv_bfloat16 tl[32][33];
    int n0 = blockIdx.x * 32, k0 = blockIdx.y * 32;
    int tx = threadIdx.x, ty = threadIdx.y;
    #pragma unroll
    for (int j = 0; j < 4; j++) {
        float v = W[(size_t)(k0 + ty + 8 * j) * Nd + n0 + tx];
        __nv_bfloat16 h = __float2bfloat16(v);
        th[ty + 8 * j][tx] = h;
        tl[ty + 8 * j][tx] = __float2bfloat16(v - __bfloat162float(h));
    }
    __syncthreads();
    #pragma unroll
    for (int j = 0; j < 4; j++) {
        hiT[(size_t)(n0 + ty + 8 * j) * Kd + k0 + tx] = th[tx][ty + 8 * j];
        loT[(size_t)(n0 + ty + 8 * j) * Kd + k0 + tx] = tl[tx][ty + 8 * j];
    }
}

// ---------------------------------------------------------------------------
// bf16-split GEMM on HMMA (R8 verbatim — validated at 253us/85us)
// ---------------------------------------------------------------------------
#define AS_LD 40
__global__ void __launch_bounds__(256, 2)
gemm_bf16_kernel(const __nv_bfloat16* __restrict__ Ah, const __nv_bfloat16* __restrict__ Al,
                 const __nv_bfloat16* __restrict__ Bh, const __nv_bfloat16* __restrict__ Bl,
                 const float* __restrict__ bias, float* __restrict__ C,
                 int M, int N, int K) {
    __shared__ __nv_bfloat16 Ash[128 * AS_LD];
    __shared__ __nv_bfloat16 Asl[128 * AS_LD];
    __shared__ __nv_bfloat16 Bsh[128 * AS_LD];
    __shared__ __nv_bfloat16 Bsl[128 * AS_LD];

    const int tid = threadIdx.x;
    const int wid = tid >> 5, lane = tid & 31;
    const int g = lane >> 2, q4 = lane & 3;
    const int wm = wid >> 2, wn = wid & 3;
    const int m0 = blockIdx.y * 128, n0 = blockIdx.x * 128;
    const int lrow = tid >> 1, loff = (tid & 1) * 16;

    const uint32_t a_off2 = (uint32_t)(((wm * 64) + ((lane >> 3) & 1) * 8 + (lane & 7)) * AS_LD
                                       + (lane >> 4) * 8) * 2;
    const uint32_t b_off2 = (uint32_t)(((wn * 32) + (lane >> 4) * 8 + (lane & 7)) * AS_LD
                                       + ((lane >> 3) & 1) * 8) * 2;

    const uint32_t sAh = smem_u32(Ash) + a_off2;
    const uint32_t sAl = smem_u32(Asl) + a_off2;
    const uint32_t sBh = smem_u32(Bsh) + b_off2;
    const uint32_t sBl = smem_u32(Bsl) + b_off2;

    float Cf[4][4][4];
    #pragma unroll
    for (int mt = 0; mt < 4; mt++)
        #pragma unroll
        for (int nt = 0; nt < 4; nt++)
            #pragma unroll
            for (int e = 0; e < 4; e++) Cf[mt][nt][e] = 0.0f;

    for (int k0 = 0; k0 < K; k0 += 32) {
        __syncthreads();
        {
            const __nv_bfloat16* pa = Ah + (size_t)(m0 + lrow) * K + k0 + loff;
            *reinterpret_cast<uint4*>(&Ash[lrow * AS_LD + loff])     = *reinterpret_cast<const uint4*>(pa);
            *reinterpret_cast<uint4*>(&Ash[lrow * AS_LD + loff + 8]) = *reinterpret_cast<const uint4*>(pa + 8);
            const __nv_bfloat16* pl = Al + (size_t)(m0 + lrow) * K + k0 + loff;
            *reinterpret_cast<uint4*>(&Asl[lrow * AS_LD + loff])     = *reinterpret_cast<const uint4*>(pl);
            *reinterpret_cast<uint4*>(&Asl[lrow * AS_LD + loff + 8]) = *reinterpret_cast<const uint4*>(pl + 8);
            const __nv_bfloat16* pb = Bh + (size_t)(n0 + lrow) * K + k0 + loff;
            *reinterpret_cast<uint4*>(&Bsh[lrow * AS_LD + loff])     = *reinterpret_cast<const uint4*>(pb);
            *reinterpret_cast<uint4*>(&Bsh[lrow * AS_LD + loff + 8]) = *reinterpret_cast<const uint4*>(pb + 8);
            const __nv_bfloat16* pc = Bl + (size_t)(n0 + lrow) * K + k0 + loff;
            *reinterpret_cast<uint4*>(&Bsl[lrow * AS_LD + loff])     = *reinterpret_cast<const uint4*>(pc);
            *reinterpret_cast<uint4*>(&Bsl[lrow * AS_LD + loff + 8]) = *reinterpret_cast<const uint4*>(pc + 8);
        }
        __syncthreads();

        #pragma unroll
        for (int ks = 0; ks < 2; ks++) {
            uint32_t bh4[2][4], bl4[2][4];
            #pragma unroll
            for (int ntp = 0; ntp < 2; ntp++) {
                ldm_x4(bh4[ntp], sBh + ntp * 1280 + ks * 32);
                ldm_x4(bl4[ntp], sBl + ntp * 1280 + ks * 32);
            }
            #pragma unroll
            for (int mt = 0; mt < 4; mt++) {
                uint32_t ah4[4], al4[4];
                ldm_x4(ah4, sAh + mt * 1280 + ks * 32);
                ldm_x4(al4, sAl + mt * 1280 + ks * 32);
                #pragma unroll
                for (int ntp = 0; ntp < 2; ntp++) {
                    mma_bf16(Cf[mt][2 * ntp],     ah4, &bh4[ntp][0]);
                    mma_bf16(Cf[mt][2 * ntp],     ah4, &bl4[ntp][0]);
                    mma_bf16(Cf[mt][2 * ntp],     al4, &bh4[ntp][0]);
                    mma_bf16(Cf[mt][2 * ntp + 1], ah4, &bh4[ntp][2]);
                    mma_bf16(Cf[mt][2 * ntp + 1], ah4, &bl4[ntp][2]);
                    mma_bf16(Cf[mt][2 * ntp + 1], al4, &bh4[ntp][2]);
                }
            }
        }
    }

    #pragma unroll
    for (int mt = 0; mt < 4; mt++) {
        int row = m0 + wm * 64 + mt * 16 + g;
        #pragma unroll
        for (int nt = 0; nt < 4; nt++) {
            int col = n0 + wn * 32 + nt * 8 + 2 * q4;
            float2 b2 = *reinterpret_cast<const float2*>(bias + col);
            float2 o0 = {Cf[mt][nt][0] + b2.x, Cf[mt][nt][1] + b2.y};
            float2 o1 = {Cf[mt][nt][2] + b2.x, Cf[mt][nt][3] + b2.y};
            *reinterpret_cast<float2*>(C + (size_t)row * N + col) = o0;
            *reinterpret_cast<float2*>(C + (size_t)(row + 8) * N + col) = o1;
        }
    }
}

// ---------------------------------------------------------------------------
// Flash attention, bf16-split HMMA + ldmatrix. Br=128 (8 warps x 16 rows),
// Bc=64. Sync loads (no cp.async). P stays in registers.
// ---------------------------------------------------------------------------
#define FLD 72
// element offsets in smem
#define OQH 0
#define OQL (128 * FLD)                 // 9216
#define OKH (2 * 128 * FLD)             // 18432
#define OKL (OKH + 64 * FLD)            // 23040
#define OVH (OKL + 64 * FLD)            // 27648
#define OVL (OVH + 64 * FLD)            // 32256
#define FLASH_SMEM ((OVL + 64 * FLD) * 2)   // 73728 B

__global__ void __launch_bounds__(256, 2)
flash_bf16_kernel(const float* __restrict__ qkv, float* __restrict__ outp) {
    extern __shared__ __nv_bfloat16 smf[];
    const uint32_t sb = smem_u32(smf);

    const int qb = (S_LEN / 128 - 1) - blockIdx.x;   // heavy tiles first
    const int h  = blockIdx.y;
    const int tid = threadIdx.x;
    const int wid = tid >> 5, lane = tid & 31;
    const int g = lane >> 2, q4 = lane & 3;
    const int qcol = h * HDIM;
    const float scale = 0.125f;

    // per-lane ldmatrix byte offsets (same derivations as validated GEMM)
    const uint32_t qoff2 = (uint32_t)(((wid * 16) + ((lane >> 3) & 1) * 8 + (lane & 7)) * FLD
                                      + (lane >> 4) * 8) * 2;
    const uint32_t koff2 = (uint32_t)(((lane >> 4) * 8 + (lane & 7)) * FLD
                                      + ((lane >> 3) & 1) * 8) * 2;
    const uint32_t voff2 = (uint32_t)((((lane >> 3) & 1) * 8 + (lane & 7)) * FLD
                                      + (lane >> 4) * 8) * 2;

    // ---- Q load: fp32 -> scaled bf16 hi/lo ----
    #pragma unroll
    for (int i = 0; i < 8; i++) {
        int p = tid + i * 256;
        int r = p >> 4, c4 = (p & 15) * 4;
        float4 q = *reinterpret_cast<const float4*>(
            qkv + (size_t)(qb * 128 + r) * N3 + qcol + c4);
        q.x *= scale; q.y *= scale; q.z *= scale; q.w *= scale;
        split_store4(smf + OQH, smf + OQL, r * FLD + c4, q);
    }

    float O[8][4];
    #pragma unroll
    for (int nt = 0; nt < 8; nt++)
        #pragma unroll
        for (int e = 0; e < 4; e++) O[nt][e] = 0.0f;
    float m0r = -1e30f, m1r = -1e30f, l0r = 0.0f, l1r = 0.0f;

    const uint32_t qbh = sb + OQH * 2 + qoff2;
    const uint32_t qbl = sb + OQL * 2 + qoff2;
    const uint32_t kbh = sb + OKH * 2 + koff2;
    const uint32_t kbl = sb + OKL * 2 + koff2;
    const uint32_t vbh = sb + OVH * 2 + voff2;
    const uint32_t vbl = sb + OVL * 2 + voff2;

    const int nkt = 2 * qb + 2;
    for (int kb = 0; kb < nkt; kb++) {
        __syncthreads();   // prior iter done reading K/V (covers Q stores on iter 0)
        // ---- K/V load: fp32 -> bf16 hi/lo ----
        #pragma unroll
        for (int i = 0; i < 4; i++) {
            int p = tid + i * 256;
            int r = p >> 4, c4 = (p & 15) * 4;
            const float* base = qkv + (size_t)(kb * 64 + r) * N3 + DMODEL + qcol;
            float4 k4 = *reinterpret_cast<const float4*>(base + c4);
            split_store4(smf + OKH, smf + OKL, r * FLD + c4, k4);
            float4 v4 = *reinterpret_cast<const float4*>(base + DMODEL + c4);
            split_store4(smf + OVH, smf + OVL, r * FLD + c4, v4);
        }
        __syncthreads();

        // ---- S = Q K^T (bf16 3-term split) ----
        float S[8][4];
        #pragma unroll
        for (int nt = 0; nt < 8; nt++)
            #pragma unroll
            for (int e = 0; e < 4; e++) S[nt][e] = 0.0f;

        #pragma unroll
        for (int ks = 0; ks < 4; ks++) {
            uint32_t qh4[4], ql4[4];
            ldm_x4(qh4, qbh + ks * 32);
            ldm_x4(ql4, qbl + ks * 32);
            #pragma unroll
            for (int ntp = 0; ntp < 4; ntp++) {
                uint32_t kh4[4], kl4[4];
                ldm_x4(kh4, kbh + ntp * 2304 + ks * 32);   // 16*FLD*2 = 2304
                ldm_x4(kl4, kbl + ntp * 2304 + ks * 32);
                mma_bf16(S[2 * ntp],     qh4, &kh4[0]);
                mma_bf16(S[2 * ntp],     qh4, &kl4[0]);
                mma_bf16(S[2 * ntp],     ql4, &kh4[0]);
                mma_bf16(S[2 * ntp + 1], qh4, &kh4[2]);
                mma_bf16(S[2 * ntp + 1], qh4, &kl4[2]);
                mma_bf16(S[2 * ntp + 1], ql4, &kh4[2]);
            }
        }

        // ---- causal mask (diagonal tiles only) ----
        if (kb >= 2 * qb) {
            int row0 = qb * 128 + wid * 16 + g;
            int row1 = row0 + 8;
            #pragma unroll
            for (int nt = 0; nt < 8; nt++) {
                int c = kb * 64 + nt * 8 + 2 * q4;
                if (c     > row0) S[nt][0] = -1e30f;
                if (c + 1 > row0) S[nt][1] = -1e30f;
                if (c     > row1) S[nt][2] = -1e30f;
                if (c + 1 > row1) S[nt][3] = -1e30f;
            }
        }

        // ---- online softmax (quad reductions) ----
        float mx0 = -1e30f, mx1 = -1e30f;
        #pragma unroll
        for (int nt = 0; nt < 8; nt++) {
            mx0 = fmaxf(mx0, fmaxf(S[nt][0], S[nt][1]));
            mx1 = fmaxf(mx1, fmaxf(S[nt][2], S[nt][3]));
        }
        mx0 = fmaxf(mx0, __shfl_xor_sync(0xffffffffu, mx0, 1));
        mx0 = fmaxf(mx0, __shfl_xor_sync(0xffffffffu, mx0, 2));
        mx1 = fmaxf(mx1, __shfl_xor_sync(0xffffffffu, mx1, 1));
        mx1 = fmaxf(mx1, __shfl_xor_sync(0xffffffffu, mx1, 2));
        float mn0 = fmaxf(m0r, mx0), mn1 = fmaxf(m1r, mx1);
        float al0 = __expf(m0r - mn0), al1 = __expf(m1r - mn1);
        float rs0 = 0.0f, rs1 = 0.0f;
        #pragma unroll
        for (int nt = 0; nt < 8; nt++) {
            S[nt][0] = __expf(S[nt][0] - mn0);
            S[nt][1] = __expf(S[nt][1] - mn0);
            S[nt][2] = __expf(S[nt][2] - mn1);
            S[nt][3] = __expf(S[nt][3] - mn1);
            rs0 += S[nt][0] + S[nt][1];
            rs1 += S[nt][2] + S[nt][3];
        }
        rs0 += __shfl_xor_sync(0xffffffffu, rs0, 1);
        rs0 += __shfl_xor_sync(0xffffffffu, rs0, 2);
        rs1 += __shfl_xor_sync(0xffffffffu, rs1, 1);
        rs1 += __shfl_xor_sync(0xffffffffu, rs1, 2);
        l0r = l0r * al0 + rs0;
        l1r = l1r * al1 + rs1;
        m0r = mn0; m1r = mn1;
        #pragma unroll
        for (int nt = 0; nt < 8; nt++) {
            O[nt][0] *= al0; O[nt][1] *= al0;
            O[nt][2] *= al1; O[nt][3] *= al1;
        }

        // ---- O += P @ V (P packed from regs; V via ldmatrix.trans) ----
        #pragma unroll
        for (int ks = 0; ks < 4; ks++) {
            uint32_t ph[4], pl[4];
            pack_pair(S[2 * ks][0],     S[2 * ks][1],     ph[0], pl[0]);
            pack_pair(S[2 * ks][2],     S[2 * ks][3],     ph[1], pl[1]);
            pack_pair(S[2 * ks + 1][0], S[2 * ks + 1][1], ph[2], pl[2]);
            pack_pair(S[2 * ks + 1][2], S[2 * ks + 1][3], ph[3], pl[3]);
            #pragma unroll
            for (int ntp = 0; ntp < 4; ntp++) {
                uint32_t vh4[4], vl4[4];
                ldm_x4_t(vh4, vbh + ks * 2304 + ntp * 32);
                ldm_x4_t(vl4, vbl + ks * 2304 + ntp * 32);
                mma_bf16(O[2 * ntp],     ph, &vh4[0]);
                mma_bf16(O[2 * ntp],     ph, &vl4[0]);
                mma_bf16(O[2 * ntp],     pl, &vh4[0]);
                mma_bf16(O[2 * ntp + 1], ph, &vh4[2]);
                mma_bf16(O[2 * ntp + 1], ph, &vl4[2]);
                mma_bf16(O[2 * ntp + 1], pl, &vh4[2]);
            }
        }
    }

    // ---- epilogue ----
    float inv0 = 1.0f / l0r, inv1 = 1.0f / l1r;
    int row0 = qb * 128 + wid * 16 + g;
    int row1 = row0 + 8;
    #pragma unroll
    for (int nt = 0; nt < 8; nt++) {
        int col = qcol + nt * 8 + 2 * q4;
        float2 o0 = {O[nt][0] * inv0, O[nt][1] * inv0};
        float2 o1 = {O[nt][2] * inv1, O[nt][3] * inv1};
        *reinterpret_cast<float2*>(outp + (size_t)row0 * DMODEL + col) = o0;
        *reinterpret_cast<float2*>(outp + (size_t)row1 * DMODEL + col) = o1;
    }
}

// ---------------------------------------------------------------------------
// Launch
// ---------------------------------------------------------------------------
extern "C" void kernel_launch(void* const* d_in, const int* in_sizes, int n_in,
                              void* d_out, int out_size) {
    const float* x      = (const float*)d_in[0];
    const float* w_qkv  = (const float*)d_in[1];
    const float* b_qkv  = (const float*)d_in[2];
    const float* w_proj = (const float*)d_in[3];
    const float* b_proj = (const float*)d_in[4];
    float* out = (float*)d_out;

    float *qkv, *attn;
    __nv_bfloat16 *xhi, *xlo, *ahi, *alo, *wqh, *wql, *wph, *wpl;
    cudaGetSymbolAddress((void**)&qkv, g_qkv);
    cudaGetSymbolAddress((void**)&attn, g_attn);
    cudaGetSymbolAddress((void**)&xhi, g_xhi);
    cudaGetSymbolAddress((void**)&xlo, g_xlo);
    cudaGetSymbolAddress((void**)&ahi, g_ahi);
    cudaGetSymbolAddress((void**)&alo, g_alo);
    cudaGetSymbolAddress((void**)&wqh, g_wqh);
    cudaGetSymbolAddress((void**)&wql, g_wql);
    cudaGetSymbolAddress((void**)&wph, g_wph);
    cudaGetSymbolAddress((void**)&wpl, g_wpl);

    cudaFuncSetAttribute(flash_bf16_kernel,
                         cudaFuncAttributeMaxDynamicSharedMemorySize, FLASH_SMEM);

    // Prep: split x; split+transpose weights
    split_kernel<<<S_LEN * DMODEL / 1024, 256>>>(x, xhi, xlo);
    splitT_kernel<<<dim3(N3 / 32, DMODEL / 32), dim3(32, 8)>>>(w_qkv, wqh, wql, DMODEL, N3);
    splitT_kernel<<<dim3(DMODEL / 32, DMODEL / 32), dim3(32, 8)>>>(w_proj, wph, wpl, DMODEL, DMODEL);

    // 1) QKV projection
    gemm_bf16_kernel<<<dim3(N3 / 128, S_LEN / 128), 256>>>(
        xhi, xlo, wqh, wql, b_qkv, qkv, S_LEN, N3, DMODEL);

    // 2) Causal flash attention (bf16-split HMMA + ldmatrix)
    flash_bf16_kernel<<<dim3(S_LEN / 128, NHEAD), 256, FLASH_SMEM>>>(qkv, attn);

    // 3) Output projection
    split_kernel<<<S_LEN * DMODEL / 1024, 256>>>(attn, ahi, alo);
    gemm_bf16_kernel<<<dim3(DMODEL / 128, S_LEN / 128), 256>>>(
        ahi, alo, wph, wpl, b_proj, out, S_LEN, DMODEL, DMODEL);
}